// round 17
// baseline (speedup 1.0000x reference)
#include <cuda_runtime.h>
#include <cuda_fp16.h>
#include <math.h>
#include <stdint.h>

#define BB   2
#define NSEQ 2048
#define DMOD 1024
#define NH   16
#define HDIM 64
#define NC   4
#define BH   (BB * NH)

// ---------------- scratch (device globals; no allocation allowed) ----------------
__device__ float  g_v[(size_t)BB * NH * NSEQ * HDIM];
__device__ __half g_bias[(size_t)BB * NSEQ * NSEQ];
__device__ float  g_bmax[(size_t)BB * NSEQ];

// fp16 operands, pre-swizzled 128x64 SW128 tiles (16KB each)
__device__ __half gXf[(size_t)4096 * 1024];
__device__ __half gWqf[(size_t)3072 * 1024];
__device__ __half gWof[(size_t)1024 * 1024];
__device__ __half gAf[(size_t)4096 * 1024];

// attention operands: single fp16, pre-swizzled tiles
__device__ __half gQf[(size_t)BH * NSEQ * HDIM];
__device__ __half gKf[(size_t)BH * NSEQ * HDIM];
__device__ __half gVtf[(size_t)BH * NSEQ * HDIM];

// ---------------- PTX helpers (base sm_103-legal only) ----------------
__device__ __forceinline__ uint32_t smem_u32(const void* p) {
    uint32_t a;
    asm("{ .reg .u64 t; cvta.to.shared.u64 t, %1; cvt.u32.u64 %0, t; }" : "=r"(a) : "l"(p));
    return a;
}

#define CP_ASYNC16(dst, src) \
    asm volatile("cp.async.cg.shared.global [%0], [%1], 16;" :: "r"(dst), "l"(src) : "memory")
#define CP_COMMIT() asm volatile("cp.async.commit_group;" ::: "memory")
#define CP_WAIT0()  asm volatile("cp.async.wait_group 0;" ::: "memory")
#define CP_WAIT1()  asm volatile("cp.async.wait_group 1;" ::: "memory")

#define LDMX4(r, a) \
    asm volatile("ldmatrix.sync.aligned.m8n8.x4.shared.b16 {%0,%1,%2,%3}, [%4];" \
        : "=r"((r)[0]), "=r"((r)[1]), "=r"((r)[2]), "=r"((r)[3]) : "r"(a))

__device__ __forceinline__ void mma_f16(float* d, uint32_t a0, uint32_t a1,
                                        uint32_t a2, uint32_t a3,
                                        uint32_t b0, uint32_t b1) {
    asm volatile(
        "mma.sync.aligned.m16n8k16.row.col.f32.f16.f16.f32 "
        "{%0,%1,%2,%3},{%4,%5,%6,%7},{%8,%9},{%0,%1,%2,%3};"
        : "+f"(d[0]), "+f"(d[1]), "+f"(d[2]), "+f"(d[3])
        : "r"(a0), "r"(a1), "r"(a2), "r"(a3), "r"(b0), "r"(b1));
}

// fp16x2 pack: first arg -> lower half
__device__ __forceinline__ uint32_t pack2_f16(float lo, float hi) {
    uint32_t r;
    asm("cvt.rn.f16x2.f32 %0, %1, %2;" : "=r"(r) : "f"(hi), "f"(lo));
    return r;
}
__device__ __forceinline__ uint32_t ex2_f16x2(uint32_t x) {
    uint32_t r;
    asm("ex2.approx.f16x2 %0, %1;" : "=r"(r) : "r"(x));
    return r;
}

#define ONES2 0x3C003C00u   // fp16x2 {1.0, 1.0}

// ---------------- merged conversion: x, wqkv, wout -> blocked swizzled fp16 tiles ----------------
__global__ void __launch_bounds__(256)
conv3_kernel(const float* __restrict__ x, const float* __restrict__ wq,
             const float* __restrict__ wo)
{
    int bI = blockIdx.x;
    const float* src;
    __half* dst;
    if (bI < 2048)      { src = x;  dst = gXf; }
    else if (bI < 3584) { src = wq; dst = gWqf; bI -= 2048; }
    else                { src = wo; dst = gWof; bI -= 3584; }

    size_t idx = ((size_t)bI * 256 + threadIdx.x) * 8;
    int r  = (int)(idx >> 10);        // K = 1024
    int c0 = (int)(idx & 1023);
    float4 v0 = *(const float4*)(src + idx);
    float4 v1 = *(const float4*)(src + idx + 4);
    uint4 w;
    w.x = pack2_f16(v0.x, v0.y);
    w.y = pack2_f16(v0.z, v0.w);
    w.z = pack2_f16(v1.x, v1.y);
    w.w = pack2_f16(v1.z, v1.w);
    int rt = r >> 7, lr = r & 127, ch = c0 >> 6, lc = c0 & 63;
    size_t tile = (size_t)rt * 16 + ch;
    uint32_t off = lr * 128 + lc * 2;
    uint32_t sw = off ^ ((off >> 3) & 0x70);
    *(uint4*)((char*)dst + tile * 16384 + sw) = w;
}

// ---------------- fp16 HMMA GEMM (round-12 config, measured 74us) ----------------
#define GEMM_SMEM (2 * 24 * 1024)

template <int MODE>
__global__ void __launch_bounds__(128, 4)
gemm_f16(const char* __restrict__ Af, const char* __restrict__ Bf,
         float* __restrict__ Cout, int KC, int Nt,
         const float* __restrict__ qw, const float* __restrict__ kw)
{
    extern __shared__ char smraw[];
    const uint32_t smemS = smem_u32(smraw);
    const int tid  = threadIdx.x;
    const int lane = tid & 31;
    const int warp = tid >> 5;
    const int jcol = blockIdx.x;

    const size_t tA0 = (size_t)blockIdx.y * KC * 16384;
    const size_t tB0 = ((size_t)(jcol >> 1) * KC) * 16384 + (size_t)(jcol & 1) * 8192;

    float acc[2][8][4];
#pragma unroll
    for (int m = 0; m < 2; m++)
#pragma unroll
        for (int j = 0; j < 8; j++)
#pragma unroll
            for (int t = 0; t < 4; t++) acc[m][j][t] = 0.f;

    const int lrow = lane & 15;
    const int cb   = (lane >> 4) << 4;

    {
        const char* sA = Af + tA0 + tid * 16;
        const char* sB = Bf + tB0 + tid * 16;
        uint32_t d0 = smemS + tid * 16;
#pragma unroll
        for (int i = 0; i < 8; i++) CP_ASYNC16(d0 + i * 2048, sA + i * 2048);
#pragma unroll
        for (int i = 0; i < 4; i++) CP_ASYNC16(d0 + 16384 + i * 2048, sB + i * 2048);
        CP_COMMIT();
    }

    for (int kc = 0; kc < KC; kc++) {
        __syncthreads();
        if (kc + 1 < KC) {
            const char* sA = Af + tA0 + (size_t)(kc + 1) * 16384 + tid * 16;
            const char* sB = Bf + tB0 + (size_t)(kc + 1) * 16384 + tid * 16;
            uint32_t d0 = smemS + ((kc + 1) & 1) * 24576 + tid * 16;
#pragma unroll
            for (int i = 0; i < 8; i++) CP_ASYNC16(d0 + i * 2048, sA + i * 2048);
#pragma unroll
            for (int i = 0; i < 4; i++) CP_ASYNC16(d0 + 16384 + i * 2048, sB + i * 2048);
            CP_COMMIT();
            CP_WAIT1();
        } else {
            CP_WAIT0();
        }
        __syncthreads();

        uint32_t buf = smemS + (kc & 1) * 24576;
        const uint32_t aS = buf, bS = buf + 16384;

#pragma unroll
        for (int ks = 0; ks < 4; ks++) {
            uint32_t af[2][4];
#pragma unroll
            for (int mf = 0; mf < 2; mf++) {
                int row = warp * 32 + mf * 16 + lrow;
                uint32_t sw = (uint32_t)(row * 128 + ks * 32 + cb) ^ ((row & 7) << 4);
                LDMX4(af[mf], aS + sw);
            }
#pragma unroll
            for (int nf2 = 0; nf2 < 4; nf2++) {
                int row = nf2 * 16 + lrow;
                uint32_t sw = (uint32_t)(row * 128 + ks * 32 + cb) ^ ((row & 7) << 4);
                uint32_t bfr[4];
                LDMX4(bfr, bS + sw);
#pragma unroll
                for (int mf = 0; mf < 2; mf++) {
                    mma_f16(acc[mf][2 * nf2],     af[mf][0], af[mf][1], af[mf][2], af[mf][3], bfr[0], bfr[2]);
                    mma_f16(acc[mf][2 * nf2 + 1], af[mf][0], af[mf][1], af[mf][2], af[mf][3], bfr[1], bfr[3]);
                }
            }
        }
    }

    const int r0l = lane >> 2;
    const int c2  = (lane & 3) * 2;

    if (MODE == 0) {
        const int n0 = jcol * 64;
#pragma unroll
        for (int mf = 0; mf < 2; mf++) {
            const int m0 = blockIdx.y * 128 + warp * 32 + mf * 16 + r0l;
#pragma unroll
            for (int nf = 0; nf < 8; nf++) {
                int n = n0 + nf * 8 + c2;
                *(float2*)(Cout + (size_t)m0 * Nt + n)       = make_float2(acc[mf][nf][0], acc[mf][nf][1]);
                *(float2*)(Cout + (size_t)(m0 + 8) * Nt + n) = make_float2(acc[mf][nf][2], acc[mf][nf][3]);
            }
        }
    } else {
        const int which = jcol >> 4;     // 0:q 1:k 2:v
        const int h = jcol & 15;
#pragma unroll
        for (int mf = 0; mf < 2; mf++) {
            const int m0 = blockIdx.y * 128 + warp * 32 + mf * 16 + r0l;
            const int m1 = m0 + 8;
            const int b0i = m0 >> 11, n0i = m0 & 2047;
            const int b1i = m1 >> 11, n1i = m1 & 2047;

            if (which == 2) {
                float* vb = g_v;
#pragma unroll
                for (int nf = 0; nf < 8; nf++) {
                    int dd = nf * 8 + c2;
                    *(float2*)&vb[(((size_t)(b0i * NH + h)) * NSEQ + n0i) * HDIM + dd] =
                        make_float2(acc[mf][nf][0], acc[mf][nf][1]);
                    *(float2*)&vb[(((size_t)(b1i * NH + h)) * NSEQ + n1i) * HDIM + dd] =
                        make_float2(acc[mf][nf][2], acc[mf][nf][3]);
                }
            } else {
                const float* w = (which == 0) ? qw : kw;
                char* df = (which == 0) ? (char*)gQf : (char*)gKf;
                float ss0 = 0.f, ss1 = 0.f;
#pragma unroll
                for (int nf = 0; nf < 8; nf++) {
                    ss0 += acc[mf][nf][0] * acc[mf][nf][0] + acc[mf][nf][1] * acc[mf][nf][1];
                    ss1 += acc[mf][nf][2] * acc[mf][nf][2] + acc[mf][nf][3] * acc[mf][nf][3];
                }
                ss0 += __shfl_xor_sync(0xffffffffu, ss0, 1);
                ss0 += __shfl_xor_sync(0xffffffffu, ss0, 2);
                ss1 += __shfl_xor_sync(0xffffffffu, ss1, 1);
                ss1 += __shfl_xor_sync(0xffffffffu, ss1, 2);
                float r0 = rsqrtf(ss0 * (1.0f / HDIM) + 1e-6f);
                float r1 = rsqrtf(ss1 * (1.0f / HDIM) + 1e-6f);

                size_t tb0 = (((size_t)(b0i * NH + h)) * 16 + (n0i >> 7)) * 16384;
                size_t tb1 = (((size_t)(b1i * NH + h)) * 16 + (n1i >> 7)) * 16384;
                int lr0 = n0i & 127, lr1 = n1i & 127;
                uint32_t x0 = (lr0 & 7) << 4, x1 = (lr1 & 7) << 4;
#pragma unroll
                for (int nf = 0; nf < 8; nf++) {
                    int dd = nf * 8 + c2;
                    float2 wv = *(const float2*)(w + dd);
                    float v0 = acc[mf][nf][0] * r0 * wv.x;
                    float v1 = acc[mf][nf][1] * r0 * wv.y;
                    float v2 = acc[mf][nf][2] * r1 * wv.x;
                    float v3 = acc[mf][nf][3] * r1 * wv.y;
                    uint32_t o0 = (lr0 * 128 + dd * 2) ^ x0;
                    uint32_t o1 = (lr1 * 128 + dd * 2) ^ x1;
                    *(uint32_t*)(df + tb0 + o0) = pack2_f16(v0, v1);
                    *(uint32_t*)(df + tb1 + o1) = pack2_f16(v2, v3);
                }
            }
        }
    }
}

// ---------------- V transpose + fp16 convert ----------------
__global__ void __launch_bounds__(256)
vsplit_kernel()
{
    __shared__ float stg[64][65];
    const int kt = blockIdx.x, bh = blockIdx.y;
    const int tid = threadIdx.x;
    {
        int s = tid >> 2, d0 = (tid & 3) * 16;
        const float* vp = g_v + ((size_t)bh * NSEQ + kt * 64 + s) * HDIM + d0;
#pragma unroll
        for (int i = 0; i < 4; i++) {
            float4 v = *(const float4*)(vp + i * 4);
            stg[s][d0 + i * 4 + 0] = v.x;
            stg[s][d0 + i * 4 + 1] = v.y;
            stg[s][d0 + i * 4 + 2] = v.z;
            stg[s][d0 + i * 4 + 3] = v.w;
        }
    }
    __syncthreads();
    {
        int dR = tid >> 2, c0 = (tid & 3) * 16;
        uint32_t hw[8];
#pragma unroll
        for (int j = 0; j < 8; j++)
            hw[j] = pack2_f16(stg[c0 + 2 * j][dR], stg[c0 + 2 * j + 1][dR]);
        size_t tb = ((size_t)bh * 32 + kt) * 8192;
        uint32_t off0 = dR * 128 + c0 * 2;
        uint32_t x = (dR & 7) << 4;
        *(uint4*)((char*)gVtf + tb + (off0 ^ x))        = make_uint4(hw[0], hw[1], hw[2], hw[3]);
        *(uint4*)((char*)gVtf + tb + ((off0 + 16) ^ x)) = make_uint4(hw[4], hw[5], hw[6], hw[7]);
    }
}

// ---------------- bias precompute: fp16 output (pairs per thread), + row max ----------------
__global__ void __launch_bounds__(256)
bias_kernel(const float* __restrict__ cm, const float* __restrict__ im)
{
    int bq = blockIdx.x;
    int b = bq / NSEQ, q = bq % NSEQ;
    const float* cmb = cm + (size_t)b * NC * NSEQ;
    float c0 = cmb[q], c1 = cmb[NSEQ + q], c2 = cmb[2 * NSEQ + q], c3 = cmb[3 * NSEQ + q];

    float sv[8];
    float mx = 0.f;
#pragma unroll
    for (int i = 0; i < 4; i++) {
        int k = (threadIdx.x + i * 256) * 2;
        float sA = c0 * cmb[k]     + c1 * cmb[NSEQ + k]     + c2 * cmb[2 * NSEQ + k]     + c3 * cmb[3 * NSEQ + k];
        float sB = c0 * cmb[k + 1] + c1 * cmb[NSEQ + k + 1] + c2 * cmb[2 * NSEQ + k + 1] + c3 * cmb[3 * NSEQ + k + 1];
        sv[2 * i] = sA; sv[2 * i + 1] = sB;
        mx = fmaxf(mx, fmaxf(sA, sB));
    }
    __shared__ float red[8];
#pragma unroll
    for (int o = 16; o > 0; o >>= 1) mx = fmaxf(mx, __shfl_xor_sync(0xffffffffu, mx, o));
    if ((threadIdx.x & 31) == 0) red[threadIdx.x >> 5] = mx;
    __syncthreads();
    if (threadIdx.x == 0) {
        float m = red[0];
#pragma unroll
        for (int wN = 1; wN < 8; wN++) m = fmaxf(m, red[wN]);
        red[0] = fmaxf(m, 1e-6f);
    }
    __syncthreads();
    float inv = 1.f / red[0];
    const float* imr = im + (size_t)bq * NSEQ;
    __half* br = g_bias + (size_t)bq * NSEQ;
    float wmax = -1e30f;
#pragma unroll
    for (int i = 0; i < 4; i++) {
        int k = (threadIdx.x + i * 256) * 2;
        float2 imv = *(const float2*)(imr + k);
        float vA = 2.f * sv[2 * i]     * inv - 1.f + 0.3f * imv.x;
        float vB = 2.f * sv[2 * i + 1] * inv - 1.f + 0.3f * imv.y;
        *(uint32_t*)((char*)br + k * 2) = pack2_f16(vA, vB);
        wmax = fmaxf(wmax, fmaxf(vA, vB));
    }
    __syncthreads();
#pragma unroll
    for (int o = 16; o > 0; o >>= 1) wmax = fmaxf(wmax, __shfl_xor_sync(0xffffffffu, wmax, o));
    if ((threadIdx.x & 31) == 0) red[threadIdx.x >> 5] = wmax;
    __syncthreads();
    if (threadIdx.x == 0) {
        float m = red[0];
#pragma unroll
        for (int wN = 1; wN < 8; wN++) m = fmaxf(m, red[wN]);
        g_bmax[bq] = m + 0.001f;   // cover fp16 rounding of stored bias
    }
}

// ---------------- fp16 HMMA flash attention — fixed-bound softmax, fp16 bias ----------------
#define ATTN2_SMEM (16384 + 2 * 16384)

__global__ void __launch_bounds__(128, 2)
attn2_kernel(const float* __restrict__ gate)
{
    extern __shared__ char smraw[];
    const uint32_t S = smem_u32(smraw);
    const uint32_t BUF0 = S + 16384;
    const int tid = threadIdx.x, lane = tid & 31, warp = tid >> 5;
    const int bh = blockIdx.y, b = bh >> 4, h = bh & 15;
    const int qt = blockIdx.x, q0 = qt * 128;
    const float LOG2E = 1.44269504f;
    const float g32 = 3.f * fminf(fmaxf(gate[h], 0.f), 1.f) * LOG2E;
    const float SC = 0.125f * LOG2E;
    const int lrow = lane & 15, cb = (lane >> 4) << 4;
    const int wrow = warp * 32;

    // prologue: Qf -> S, KV0 -> BUF0
    {
        size_t qoff = ((size_t)(bh * 16 + qt)) * 16384 + tid * 16;
        uint32_t dq = S + tid * 16;
#pragma unroll
        for (int i = 0; i < 8; i++)
            CP_ASYNC16(dq + i * 2048, (const char*)gQf + qoff + i * 2048);
        size_t koff = ((size_t)(bh * 16)) * 16384 + tid * 16;
        size_t voff = ((size_t)(bh * 32)) * 8192 + tid * 16;
        uint32_t dk = BUF0 + tid * 16;
#pragma unroll
        for (int i = 0; i < 4; i++) {
            CP_ASYNC16(dk + i * 2048,        (const char*)gKf  + koff + i * 2048);
            CP_ASYNC16(dk + 8192 + i * 2048, (const char*)gVtf + voff + i * 2048);
        }
        CP_COMMIT();
    }

    const int r0l = lane >> 2;
    float Mrow[4];
    const __half* biasP[4];
#pragma unroll
    for (int rr = 0; rr < 4; rr++) {
        int qrow = q0 + wrow + (rr >> 1) * 16 + (rr & 1) * 8 + r0l;
        biasP[rr] = g_bias + ((size_t)(b * NSEQ + qrow)) * NSEQ;
        Mrow[rr] = 8.f * SC + g32 * g_bmax[b * NSEQ + qrow];
    }

    CP_WAIT0();
    __syncthreads();

    uint32_t qf[2][4][4];
#pragma unroll
    for (int mf = 0; mf < 2; mf++) {
        int qrow = wrow + mf * 16 + lrow;
        uint32_t qswz = (uint32_t)((qrow & 7) << 4);
#pragma unroll
        for (int ks = 0; ks < 4; ks++) {
            uint32_t sw = (uint32_t)(qrow * 128 + ks * 32 + cb) ^ qswz;
            LDMX4(qf[mf][ks], S + sw);
        }
    }

    float o[2][8][4];
    float lacc[2][4];
#pragma unroll
    for (int mf = 0; mf < 2; mf++) {
#pragma unroll
        for (int nf = 0; nf < 8; nf++)
#pragma unroll
            for (int t = 0; t < 4; t++) o[mf][nf][t] = 0.f;
#pragma unroll
        for (int t = 0; t < 4; t++) lacc[mf][t] = 0.f;
    }

    for (int kt = 0; kt < 32; kt++) {
        __syncthreads();
        if (kt + 1 < 32) {
            int k2 = kt + 1;
            size_t koff = ((size_t)(bh * 16 + (k2 >> 1))) * 16384 + (size_t)(k2 & 1) * 8192 + tid * 16;
            size_t voff = ((size_t)(bh * 32 + k2)) * 8192 + tid * 16;
            uint32_t d = BUF0 + (k2 & 1) * 16384 + tid * 16;
#pragma unroll
            for (int i = 0; i < 4; i++) {
                CP_ASYNC16(d + i * 2048,        (const char*)gKf  + koff + i * 2048);
                CP_ASYNC16(d + 8192 + i * 2048, (const char*)gVtf + voff + i * 2048);
            }
            CP_COMMIT();
            CP_WAIT1();
        } else {
            CP_WAIT0();
        }
        __syncthreads();

        uint32_t buf = BUF0 + (kt & 1) * 16384;

        // --- S = Q K^T ---
        float sf[2][8][4];
#pragma unroll
        for (int mf = 0; mf < 2; mf++)
#pragma unroll
            for (int nf = 0; nf < 8; nf++)
#pragma unroll
                for (int t = 0; t < 4; t++) sf[mf][nf][t] = 0.f;

#pragma unroll
        for (int ks = 0; ks < 4; ks++) {
#pragma unroll
            for (int nf2 = 0; nf2 < 4; nf2++) {
                int row = nf2 * 16 + lrow;
                uint32_t sw = (uint32_t)(row * 128 + ks * 32 + cb) ^ ((row & 7) << 4);
                uint32_t kf[4];
                LDMX4(kf, buf + sw);
#pragma unroll
                for (int mf = 0; mf < 2; mf++) {
                    mma_f16(sf[mf][2 * nf2],     qf[mf][ks][0], qf[mf][ks][1], qf[mf][ks][2], qf[mf][ks][3], kf[0], kf[2]);
                    mma_f16(sf[mf][2 * nf2 + 1], qf[mf][ks][0], qf[mf][ks][1], qf[mf][ks][2], qf[mf][ks][3], kf[1], kf[3]);
                }
            }
        }

        // --- fixed-bound softmax: P = 2^(S*SC + g32*bias - M); l via ones-MMA ---
        int colbase = kt * 64 + 2 * (lane & 3);
        uint32_t pf[2][4][4];
#pragma unroll
        for (int mf = 0; mf < 2; mf++) {
            const float M0 = Mrow[2 * mf], M1 = Mrow[2 * mf + 1];
#pragma unroll
            for (int kk = 0; kk < 4; kk++) {
                const int na = 2 * kk, nb = 2 * kk + 1;
                float2 ba0 = __half22float2(*(const __half2*)((const char*)biasP[2 * mf]     + (colbase + na * 8) * 2));
                float2 ba1 = __half22float2(*(const __half2*)((const char*)biasP[2 * mf + 1] + (colbase + na * 8) * 2));
                float2 bb0 = __half22float2(*(const __half2*)((const char*)biasP[2 * mf]     + (colbase + nb * 8) * 2));
                float2 bb1 = __half22float2(*(const __half2*)((const char*)biasP[2 * mf + 1] + (colbase + nb * 8) * 2));
                float t0 = fmaf(sf[mf][na][0], SC, fmaf(g32, ba0.x, -M0));
                float t1 = fmaf(sf[mf][na][1], SC, fmaf(g32, ba0.y, -M0));
                float t2 = fmaf(sf[mf][na][2], SC, fmaf(g32, ba1.x, -M1));
                float t3 = fmaf(sf[mf][na][3], SC, fmaf(g32, ba1.y, -M1));
                float u0 = fmaf(sf[mf][nb][0], SC, fmaf(g32, bb0.x, -M0));
                float u1 = fmaf(sf[mf][nb][1], SC, fmaf(g32, bb0.y, -M0));
                float u2 = fmaf(sf[mf][nb][2], SC, fmaf(g32, bb1.x, -M1));
                float u3 = fmaf(sf[mf][nb][3], SC, fmaf(g32, bb1.y, -M1));
                pf[mf][kk][0] = ex2_f16x2(pack2_f16(t0, t1));
                pf[mf][kk][1] = ex2_f16x2(pack2_f16(t2, t3));
                pf[mf][kk][2] = ex2_f16x2(pack2_f16(u0, u1));
                pf[mf][kk][3] = ex2_f16x2(pack2_f16(u2, u3));
                mma_f16(lacc[mf], pf[mf][kk][0], pf[mf][kk][1], pf[mf][kk][2], pf[mf][kk][3], ONES2, ONES2);
            }
        }

        // --- O += P V (no rescale) ---
        const uint32_t vFs = buf + 8192;
#pragma unroll
        for (int kk = 0; kk < 4; kk++) {
#pragma unroll
            for (int nf2 = 0; nf2 < 4; nf2++) {
                int row = nf2 * 16 + lrow;
                uint32_t sw = (uint32_t)(row * 128 + kk * 32 + cb) ^ ((row & 7) << 4);
                uint32_t vf[4];
                LDMX4(vf, vFs + sw);
#pragma unroll
                for (int mf = 0; mf < 2; mf++) {
                    mma_f16(o[mf][2 * nf2],     pf[mf][kk][0], pf[mf][kk][1], pf[mf][kk][2], pf[mf][kk][3], vf[0], vf[2]);
                    mma_f16(o[mf][2 * nf2 + 1], pf[mf][kk][0], pf[mf][kk][1], pf[mf][kk][2], pf[mf][kk][3], vf[1], vf[3]);
                }
            }
        }
    }

    // epilogue: normalize + write fp16 swizzled A-tile for the out-projection
    size_t tb = (((size_t)(b * 16 + qt)) * 16 + h) * 16384;
#pragma unroll
    for (int mf = 0; mf < 2; mf++) {
        float i0 = 1.f / lacc[mf][0], i1 = 1.f / lacc[mf][2];
        int lr0 = wrow + mf * 16 + r0l, lr1 = lr0 + 8;
        uint32_t x0 = (lr0 & 7) << 4, x1 = (lr1 & 7) << 4;
#pragma unroll
        for (int nf = 0; nf < 8; nf++) {
            int dd = nf * 8 + 2 * (lane & 3);
            uint32_t o0 = (lr0 * 128 + dd * 2) ^ x0;
            uint32_t o1 = (lr1 * 128 + dd * 2) ^ x1;
            *(uint32_t*)((char*)gAf + tb + o0) = pack2_f16(o[mf][nf][0] * i0, o[mf][nf][1] * i0);
            *(uint32_t*)((char*)gAf + tb + o1) = pack2_f16(o[mf][nf][2] * i1, o[mf][nf][3] * i1);
        }
    }
}

// ---------------- launch ----------------
extern "C" void kernel_launch(void* const* d_in, const int* in_sizes, int n_in,
                              void* d_out, int out_size)
{
    (void)in_sizes; (void)n_in; (void)out_size;
    const float* x    = (const float*)d_in[0];
    const float* cm   = (const float*)d_in[1];
    const float* im   = (const float*)d_in[2];
    const float* wqkv = (const float*)d_in[3];
    const float* wout = (const float*)d_in[4];
    const float* qnw  = (const float*)d_in[5];
    const float* knw  = (const float*)d_in[6];
    const float* gate = (const float*)d_in[7];
    float* out = (float*)d_out;

    void *xf, *wqf, *wof, *af;
    cudaGetSymbolAddress(&xf, gXf);
    cudaGetSymbolAddress(&wqf, gWqf);
    cudaGetSymbolAddress(&wof, gWof);
    cudaGetSymbolAddress(&af, gAf);

    cudaFuncSetAttribute(attn2_kernel, cudaFuncAttributeMaxDynamicSharedMemorySize, ATTN2_SMEM);
    cudaFuncSetAttribute(gemm_f16<0>, cudaFuncAttributeMaxDynamicSharedMemorySize, GEMM_SMEM);
    cudaFuncSetAttribute(gemm_f16<1>, cudaFuncAttributeMaxDynamicSharedMemorySize, GEMM_SMEM);

    const int M = BB * NSEQ;   // 4096

    // 1) convert all fp32 operands to fp16 swizzled tiles (one launch)
    conv3_kernel<<<4096, 256>>>(x, wqkv, wout);

    // 2) QKV projection (fp16 HMMA) with fused RMSNorm + fp16 q/k epilogue
    gemm_f16<1><<<dim3(3 * DMOD / 64, M / 128), 128, GEMM_SMEM>>>(
        (const char*)xf, (const char*)wqf, nullptr, 1024 / 64, 3 * DMOD, qnw, knw);

    // 3) V -> transposed fp16 tiles
    vsplit_kernel<<<dim3(NSEQ / 64, BH), 256>>>();

    // 4) bias precompute (fp16 output + per-row max)
    bias_kernel<<<BB * NSEQ, 256>>>(cm, im);

    // 5) fp16 HMMA flash attention (fixed-bound softmax, fp16 bias)
    attn2_kernel<<<dim3(NSEQ / 128, BH), 128, ATTN2_SMEM>>>(gate);

    // 6) out-projection (fp16 HMMA) straight into d_out
    gemm_f16<0><<<dim3(DMOD / 64, M / 128), 128, GEMM_SMEM>>>(
        (const char*)af, (const char*)wof, out, 1024 / 64, DMOD, nullptr, nullptr);
}